// round 6
// baseline (speedup 1.0000x reference)
#include <cuda_runtime.h>
#include <cstdint>

#define U_ 128
#define C_ 64
#define B_ 16
#define T_ 128
#define RANKS 8          // CTAs per cluster
#define QB 4             // batches per CTA (thread groups of 128)
#define JPC 16           // post-neurons owned per CTA (per batch slot)
#define IPL 16           // pre-neurons per lane (128 / 8)
#define CPL 8            // sensory channels per lane (64 / 8)
#define NTH (128*QB)
#define UNFOLDS 6
#define EPS_ 1e-8f
#define TX_V 512u        // bytes per v-set arriving per batch slot: 128 msgs * 4B

// dynamic SMEM layout (floats): [QB][T_][C_] x | [QB][3][U_] v | [QB][3] mbar(u64)
#define SMEM_X_FLOATS   (QB * T_ * C_)
#define SMEM_V_FLOATS   (QB * 3 * U_)
#define SMEM_BYTES      ((SMEM_X_FLOATS + SMEM_V_FLOATS) * 4 + QB * 3 * 8 + 16)

// ---------------- device scratch (no allocations allowed) ----------------
__device__ float g_rsK[U_*U_];   //  sigma * 0.5
__device__ float g_rcK[U_*U_];   // -sigma * mu * 0.5
__device__ float g_rwE[U_*U_];   //  softplus(w) * erev * 0.5
__device__ float g_ssK[C_*U_];   //  ssigma * iw * 0.5
__device__ float g_scK[C_*U_];   //  ssigma * (ib - smu) * 0.5
__device__ float g_swE[C_*U_];   //  softplus(sw) * serev * 0.5
__device__ float g_cmt[U_];      //  softplus(cm) * 6
__device__ float g_AA[U_];       //  cmt + softplus(gleak)
__device__ float g_CC[U_];       //  softplus(gleak) * vleak

__device__ __forceinline__ float softplus_f(float x) {
    return fmaxf(x, 0.0f) + log1pf(expf(-fabsf(x)));
}

__global__ void ltc_prep(const float* __restrict__ sigma, const float* __restrict__ mu,
                         const float* __restrict__ w,     const float* __restrict__ erev,
                         const float* __restrict__ ssig,  const float* __restrict__ smu,
                         const float* __restrict__ sw,    const float* __restrict__ serev,
                         const float* __restrict__ iw,    const float* __restrict__ ib,
                         const float* __restrict__ gleak, const float* __restrict__ vleak,
                         const float* __restrict__ cm)
{
    int idx = blockIdx.x * blockDim.x + threadIdx.x;
    if (idx < U_*U_) {
        float sg = sigma[idx];
        g_rsK[idx] =  sg * 0.5f;
        g_rcK[idx] = -sg * mu[idx] * 0.5f;
        g_rwE[idx] =  softplus_f(w[idx]) * erev[idx] * 0.5f;
    }
    if (idx < C_*U_) {
        int c = idx / U_;
        float sg = ssig[idx];
        g_ssK[idx] = sg * iw[c] * 0.5f;
        g_scK[idx] = sg * (ib[c] - smu[idx]) * 0.5f;
        g_swE[idx] = softplus_f(sw[idx]) * serev[idx] * 0.5f;
    }
    if (idx < U_) {
        float gl  = softplus_f(gleak[idx]);
        float cmt = softplus_f(cm[idx]) * (float)UNFOLDS;
        g_cmt[idx] = cmt;
        g_AA[idx]  = cmt + gl;
        g_CC[idx]  = gl * vleak[idx];
    }
}

// ---------------- PTX helpers ----------------
__device__ __forceinline__ uint32_t smem_u32(const void* p) {
    uint32_t a;
    asm("{ .reg .u64 t; cvta.to.shared.u64 t, %1; cvt.u32.u64 %0, t; }" : "=r"(a) : "l"(p));
    return a;
}
__device__ __forceinline__ uint32_t mapa_u32(uint32_t a, uint32_t r) {
    uint32_t o;
    asm("mapa.shared::cluster.u32 %0, %1, %2;" : "=r"(o) : "r"(a), "r"(r));
    return o;
}
__device__ __forceinline__ void cluster_sync_() {
    asm volatile("barrier.cluster.arrive.aligned;" ::: "memory");
    asm volatile("barrier.cluster.wait.aligned;"   ::: "memory");
}
__device__ __forceinline__ float tanhf_a(float x) { float y; asm("tanh.approx.f32 %0, %1;" : "=f"(y) : "f"(x)); return y; }
__device__ __forceinline__ float rcpf_(float x)   { float y; asm("rcp.approx.f32 %0, %1;"  : "=f"(y) : "f"(x)); return y; }

__device__ __forceinline__ void mbar_init_(uint32_t mb, uint32_t cnt) {
    asm volatile("mbarrier.init.shared.b64 [%0], %1;" :: "r"(mb), "r"(cnt) : "memory");
}
__device__ __forceinline__ void mbar_expect_(uint32_t mb, uint32_t bytes) {
    asm volatile("mbarrier.arrive.expect_tx.shared.b64 _, [%0], %1;" :: "r"(mb), "r"(bytes) : "memory");
}
__device__ __forceinline__ void mbar_wait_(uint32_t mb, uint32_t parity) {
    uint32_t done;
    asm volatile(
        "{\n\t.reg .pred p;\n\t"
        "mbarrier.try_wait.parity.acquire.cta.shared::cta.b64 p, [%1], %2;\n\t"
        "selp.b32 %0, 1, 0, p;\n\t}"
        : "=r"(done) : "r"(mb), "r"(parity) : "memory");
    if (!done) {
        asm volatile(
            "{\n\t.reg .pred P1;\n\t"
            "WL_%=:\n\t"
            "mbarrier.try_wait.parity.acquire.cta.shared::cta.b64 P1, [%0], %1, 0x989680;\n\t"
            "@P1 bra.uni WD_%=;\n\t"
            "bra.uni WL_%=;\n\t"
            "WD_%=:\n\t}"
            :: "r"(mb), "r"(parity) : "memory");
    }
}
// async 4-byte store into a peer CTA's SMEM, tx-counted on the peer's mbarrier
__device__ __forceinline__ void st_async_f32(uint32_t addr, float v, uint32_t mb) {
    asm volatile("st.async.shared::cluster.mbarrier::complete_tx::bytes.b32 [%0], %1, [%2];"
                 :: "r"(addr), "f"(v), "r"(mb) : "memory");
}

// ---------------- main kernel ----------------
// One cluster (8 CTAs) per GROUP of 4 batches. Thread group q (128 threads)
// runs batch g*4+q independently: its own mbarriers, v-buffers, x slice.
// While one batch's chain waits on DSMEM transit, the other 3 issue compute.
__global__ void __cluster_dims__(RANKS, 1, 1) __launch_bounds__(NTH, 1)
ltc_main(const float* __restrict__ x, const float* __restrict__ h0,
         const float* __restrict__ ow, const float* __restrict__ ob,
         float* __restrict__ out)
{
    extern __shared__ __align__(16) float dsm[];

    const int tid  = threadIdx.x;
    const int q    = tid >> 7;          // batch slot 0..3
    const int lt   = tid & 127;         // thread within slot
    const int g    = blockIdx.x / RANKS;
    const int rank = blockIdx.x % RANKS;
    const int b    = g * QB + q;        // global batch
    const int jj   = lt >> 3;           // local post-neuron (0..15)
    const int s    = lt & 7;            // lane within j-group (0..7)
    const int jg   = rank * JPC + jj;   // global post-neuron

    float*    sX  = dsm + q * (T_ * C_);                        // [T_][C_]
    float*    sVb = dsm + SMEM_X_FLOATS + q * (3 * U_);         // [3][U_]
    uint64_t* mbq = (uint64_t*)(dsm + SMEM_X_FLOATS + SMEM_V_FLOATS) + q * 3;

    // ---- weights into registers (live across entire run) ----
    float rs[IPL], rc[IPL], rw[IPL];
    #pragma unroll
    for (int k = 0; k < IPL; k++) {
        int idx = (s * IPL + k) * U_ + jg;
        rs[k] = g_rsK[idx]; rc[k] = g_rcK[idx]; rw[k] = g_rwE[idx];
    }
    float ssk[CPL], sck[CPL], swe[CPL];
    #pragma unroll
    for (int k = 0; k < CPL; k++) {
        int idx = (s * CPL + k) * U_ + jg;
        ssk[k] = g_ssK[idx]; sck[k] = g_scK[idx]; swe[k] = g_swE[idx];
    }
    const float pcm = g_cmt[jg], pa = g_AA[jg], pcc = g_CC[jg];
    const float pow_ = ow[jg], pob_ = ob[jg];

    // stage this slot's x[b] into SMEM (float4)
    {
        const float4* xg = (const float4*)(x + (size_t)b * T_ * C_);
        float4* xs = (float4*)sX;
        #pragma unroll 4
        for (int i = lt; i < T_ * C_ / 4; i += 128) xs[i] = xg[i];
    }
    sVb[lt] = h0[b * U_ + lt];          // v-set 0

    const uint32_t mbL[3] = { smem_u32(&mbq[0]), smem_u32(&mbq[1]), smem_u32(&mbq[2]) };
    if (lt == 0) {
        #pragma unroll
        for (int m = 0; m < 3; m++) { mbar_init_(mbL[m], 1); mbar_expect_(mbL[m], TX_V); }
    }
    __syncthreads();
    cluster_sync_();                    // all slots' mbarriers armed cluster-wide

    // remote addresses: lane s delivers this group's v to rank s (same slot q)
    uint32_t addrV[3], mbR[3];
    #pragma unroll
    for (int m = 0; m < 3; m++) {
        addrV[m] = mapa_u32(smem_u32(&sVb[m * U_ + jg]), (uint32_t)s);
        mbR[m]   = mapa_u32(mbL[m], (uint32_t)s);
    }

    uint32_t ph[3] = { 0, 0, 0 };
    float vlast = 0.f;

    for (int t = 0; t < T_; t++) {
        // ---- sensory partials (local; off the inter-CTA critical path) ----
        float xn = 0.f, xd = 0.f;
        #pragma unroll
        for (int k = 0; k < CPL; k++) {
            float xv = sX[t * C_ + s * CPL + k];
            float tt = tanhf_a(fmaf(ssk[k], xv, sck[k]));
            float p  = fmaf(swe[k], tt, swe[k]);   // w_pos*erev*sigmoid
            xn += p; xd += fabsf(p);
        }

        #pragma unroll
        for (int u = 0; u < UNFOLDS; u++) {
            const int m  = u % 3;            // buffer holding v-set 6t+u
            const int mw = (u + 1) % 3;      // buffer receiving v-set 6t+u+1
            if (u != 0 || t != 0) {
                mbar_wait_(mbL[m], ph[m]); ph[m] ^= 1;
                if (lt == 0) mbar_expect_(mbL[m], TX_V);   // re-arm for next phase
            }
            // recurrent partial over my 16 pre-neurons (sensory folded in)
            float rn = xn, rd = xd;
            const float4* vb = (const float4*)&sVb[m * U_ + s * IPL];
            #pragma unroll
            for (int c = 0; c < 4; c++) {
                float4 v4 = vb[c];
                #pragma unroll
                for (int k = 0; k < 4; k++) {
                    float vi = (k == 0) ? v4.x : (k == 1) ? v4.y : (k == 2) ? v4.z : v4.w;
                    float tt = tanhf_a(fmaf(rs[c*4+k], vi, rc[c*4+k]));
                    float p  = fmaf(rw[c*4+k], tt, rw[c*4+k]);
                    rn += p; rd += fabsf(p);
                }
            }
            // butterfly over the 8-lane group (all lanes end with full sums)
            #pragma unroll
            for (int d = 4; d >= 1; d >>= 1) {
                rn += __shfl_xor_sync(0xffffffffu, rn, d);
                rd += __shfl_xor_sync(0xffffffffu, rd, d);
            }
            // finalize v (every lane, redundantly)
            float vv   = sVb[m * U_ + jg];
            float num  = fmaf(pcm, vv, pcc) + rn;
            float den  = pa + rd + EPS_;
            float vnew = num * rcpf_(den);
            // broadcast: lane s sends this group's v to rank s (skip final set)
            if (t != T_ - 1 || u != UNFOLDS - 1)
                st_async_f32(addrV[mw], vnew, mbR[mw]);
            if (u == UNFOLDS - 1) {
                if (s == 0) out[((size_t)b * T_ + t) * U_ + jg] = fmaf(vnew, pow_, pob_);
                vlast = vnew;
            }
        }
    }
    if (s == 0) out[(size_t)B_ * T_ * U_ + b * U_ + jg] = vlast;   // h_final
    cluster_sync_();
}

// ---------------- launch ----------------
extern "C" void kernel_launch(void* const* d_in, const int* in_sizes, int n_in,
                              void* d_out, int out_size)
{
    const float* x     = (const float*)d_in[0];
    const float* h0    = (const float*)d_in[1];
    const float* gleak = (const float*)d_in[2];
    const float* vleak = (const float*)d_in[3];
    const float* cm    = (const float*)d_in[4];
    const float* sigma = (const float*)d_in[5];
    const float* mu    = (const float*)d_in[6];
    const float* w     = (const float*)d_in[7];
    const float* erev  = (const float*)d_in[8];
    const float* ssig  = (const float*)d_in[9];
    const float* smu   = (const float*)d_in[10];
    const float* sw    = (const float*)d_in[11];
    const float* serev = (const float*)d_in[12];
    const float* iw    = (const float*)d_in[13];
    const float* ib    = (const float*)d_in[14];
    const float* ow    = (const float*)d_in[15];
    const float* ob    = (const float*)d_in[16];

    ltc_prep<<<64, 256>>>(sigma, mu, w, erev, ssig, smu, sw, serev, iw, ib, gleak, vleak, cm);

    static bool attr_done = false;
    if (!attr_done) {
        cudaFuncSetAttribute(ltc_main, cudaFuncAttributeMaxDynamicSharedMemorySize, SMEM_BYTES);
        attr_done = true;
    }
    ltc_main<<<(B_ / QB) * RANKS, NTH, SMEM_BYTES>>>(x, h0, ow, ob, (float*)d_out);
}

// round 7
// speedup vs baseline: 1.8346x; 1.8346x over previous
#include <cuda_runtime.h>
#include <cstdint>

#define U_ 128
#define C_ 64
#define B_ 16
#define T_ 128
#define RANKS 8          // CTAs per cluster (one cluster per batch)
#define JPC 16           // post-neurons owned per CTA
#define LPJ 16           // lanes per post-neuron
#define IPL 8            // pre-neurons per lane (128 / 16)
#define CPL 4            // sensory channels per lane (64 / 16)
#define NTH 256
#define UNFOLDS 6
#define EPS_ 1e-8f
#define TX_V 512u        // bytes per v-set arriving at each CTA: 128 msgs * 4B

// ---------------- device scratch (no allocations allowed) ----------------
__device__ float g_rsK[U_*U_];   //  sigma * 0.5
__device__ float g_rcK[U_*U_];   // -sigma * mu * 0.5
__device__ float g_rwE[U_*U_];   //  softplus(w) * erev * 0.5
__device__ float g_ssK[C_*U_];   //  ssigma * iw * 0.5
__device__ float g_scK[C_*U_];   //  ssigma * (ib - smu) * 0.5
__device__ float g_swE[C_*U_];   //  softplus(sw) * serev * 0.5
__device__ float g_cmt[U_];      //  softplus(cm) * 6
__device__ float g_AA[U_];       //  cmt + softplus(gleak)
__device__ float g_CC[U_];       //  softplus(gleak) * vleak

__device__ __forceinline__ float softplus_f(float x) {
    return fmaxf(x, 0.0f) + log1pf(expf(-fabsf(x)));
}

__global__ void ltc_prep(const float* __restrict__ sigma, const float* __restrict__ mu,
                         const float* __restrict__ w,     const float* __restrict__ erev,
                         const float* __restrict__ ssig,  const float* __restrict__ smu,
                         const float* __restrict__ sw,    const float* __restrict__ serev,
                         const float* __restrict__ iw,    const float* __restrict__ ib,
                         const float* __restrict__ gleak, const float* __restrict__ vleak,
                         const float* __restrict__ cm)
{
    int idx = blockIdx.x * blockDim.x + threadIdx.x;
    if (idx < U_*U_) {
        float sg = sigma[idx];
        g_rsK[idx] =  sg * 0.5f;
        g_rcK[idx] = -sg * mu[idx] * 0.5f;
        g_rwE[idx] =  softplus_f(w[idx]) * erev[idx] * 0.5f;
    }
    if (idx < C_*U_) {
        int c = idx / U_;
        float sg = ssig[idx];
        g_ssK[idx] = sg * iw[c] * 0.5f;
        g_scK[idx] = sg * (ib[c] - smu[idx]) * 0.5f;
        g_swE[idx] = softplus_f(sw[idx]) * serev[idx] * 0.5f;
    }
    if (idx < U_) {
        float gl  = softplus_f(gleak[idx]);
        float cmt = softplus_f(cm[idx]) * (float)UNFOLDS;
        g_cmt[idx] = cmt;
        g_AA[idx]  = cmt + gl;
        g_CC[idx]  = gl * vleak[idx];
    }
}

// ---------------- PTX helpers ----------------
__device__ __forceinline__ uint32_t smem_u32(const void* p) {
    uint32_t a;
    asm("{ .reg .u64 t; cvta.to.shared.u64 t, %1; cvt.u32.u64 %0, t; }" : "=r"(a) : "l"(p));
    return a;
}
__device__ __forceinline__ uint32_t mapa_u32(uint32_t a, uint32_t r) {
    uint32_t o;
    asm("mapa.shared::cluster.u32 %0, %1, %2;" : "=r"(o) : "r"(a), "r"(r));
    return o;
}
__device__ __forceinline__ void cluster_sync_() {
    asm volatile("barrier.cluster.arrive.aligned;" ::: "memory");
    asm volatile("barrier.cluster.wait.aligned;"   ::: "memory");
}
__device__ __forceinline__ float tanhf_a(float x) { float y; asm("tanh.approx.f32 %0, %1;" : "=f"(y) : "f"(x)); return y; }
__device__ __forceinline__ float rcpf_(float x)   { float y; asm("rcp.approx.f32 %0, %1;"  : "=f"(y) : "f"(x)); return y; }

__device__ __forceinline__ void mbar_init_(uint32_t mb, uint32_t cnt) {
    asm volatile("mbarrier.init.shared.b64 [%0], %1;" :: "r"(mb), "r"(cnt) : "memory");
}
__device__ __forceinline__ void mbar_expect_(uint32_t mb, uint32_t bytes) {
    asm volatile("mbarrier.arrive.expect_tx.shared.b64 _, [%0], %1;" :: "r"(mb), "r"(bytes) : "memory");
}
__device__ __forceinline__ void mbar_wait_(uint32_t mb, uint32_t parity) {
    uint32_t done;
    asm volatile(
        "{\n\t.reg .pred p;\n\t"
        "mbarrier.try_wait.parity.acquire.cta.shared::cta.b64 p, [%1], %2;\n\t"
        "selp.b32 %0, 1, 0, p;\n\t}"
        : "=r"(done) : "r"(mb), "r"(parity) : "memory");
    if (!done) {
        asm volatile(
            "{\n\t.reg .pred P1;\n\t"
            "WL_%=:\n\t"
            "mbarrier.try_wait.parity.acquire.cta.shared::cta.b64 P1, [%0], %1, 0x989680;\n\t"
            "@P1 bra.uni WD_%=;\n\t"
            "bra.uni WL_%=;\n\t"
            "WD_%=:\n\t}"
            :: "r"(mb), "r"(parity) : "memory");
    }
}
// async 4-byte store into a peer CTA's SMEM, tx-counted on the peer's mbarrier
__device__ __forceinline__ void st_async_f32(uint32_t addr, float v, uint32_t mb) {
    asm volatile("st.async.shared::cluster.mbarrier::complete_tx::bytes.b32 [%0], %1, [%2];"
                 :: "r"(addr), "f"(v), "r"(mb) : "memory");
}

// ---------------- main kernel: one cluster (8 CTAs) per batch ----------------
// CTA `rank` owns post-neurons j in [rank*16, rank*16+16). 16 lanes per j,
// 8 pre-neurons per lane; 2 warps/SMSP cover each other's issue/dep stalls.
// Only finished v values cross the cluster (scalar st.async from 8 lanes/group).
__global__ void __cluster_dims__(RANKS, 1, 1) __launch_bounds__(NTH, 1)
ltc_main(const float* __restrict__ x, const float* __restrict__ h0,
         const float* __restrict__ ow, const float* __restrict__ ob,
         float* __restrict__ out)
{
    __shared__ __align__(16) float sV[3][U_];   // triple-buffered v-sets
    __shared__ float sX[T_][C_];                // full input slice for this batch (32 KB)
    __shared__ __align__(8) uint64_t mbar[3];

    const int tid  = threadIdx.x;
    const int b    = blockIdx.x / RANKS;
    const int rank = blockIdx.x % RANKS;
    const int jj   = tid >> 4;         // local post-neuron (0..15)
    const int s    = tid & 15;         // lane within j-group (0..15)
    const int jg   = rank * JPC + jj;  // global post-neuron

    // ---- weights into registers (live across entire run) ----
    float rs[IPL], rc[IPL], rw[IPL];
    #pragma unroll
    for (int k = 0; k < IPL; k++) {
        int idx = (s * IPL + k) * U_ + jg;
        rs[k] = g_rsK[idx]; rc[k] = g_rcK[idx]; rw[k] = g_rwE[idx];
    }
    float ssk[CPL], sck[CPL], swe[CPL];
    #pragma unroll
    for (int k = 0; k < CPL; k++) {
        int idx = (s * CPL + k) * U_ + jg;
        ssk[k] = g_ssK[idx]; sck[k] = g_scK[idx]; swe[k] = g_swE[idx];
    }
    const float pcm = g_cmt[jg], pa = g_AA[jg], pcc = g_CC[jg];
    const float pow_ = ow[jg], pob_ = ob[jg];

    // stage x[b] into SMEM (float4)
    {
        const float4* xg = (const float4*)(x + (size_t)b * T_ * C_);
        float4* xs = (float4*)&sX[0][0];
        #pragma unroll 4
        for (int i = tid; i < T_ * C_ / 4; i += NTH) xs[i] = xg[i];
    }
    if (tid < U_) sV[0][tid] = h0[b * U_ + tid];   // v-set 0

    const uint32_t mbL[3] = { smem_u32(&mbar[0]), smem_u32(&mbar[1]), smem_u32(&mbar[2]) };
    if (tid == 0) {
        #pragma unroll
        for (int m = 0; m < 3; m++) { mbar_init_(mbL[m], 1); mbar_expect_(mbL[m], TX_V); }
    }
    __syncthreads();
    cluster_sync_();                   // all mbarriers armed before any st.async

    // remote addresses: lanes 0..7 of each group deliver the group's v to rank s
    uint32_t addrV[3], mbR[3];
    const uint32_t destRank = (uint32_t)(s & 7);
    #pragma unroll
    for (int m = 0; m < 3; m++) {
        addrV[m] = mapa_u32(smem_u32(&sV[m][jg]), destRank);
        mbR[m]   = mapa_u32(mbL[m], destRank);
    }
    const bool sender = (s < 8);

    uint32_t ph[3] = { 0, 0, 0 };
    float vlast = 0.f;

    for (int t = 0; t < T_; t++) {
        // ---- sensory partials (local; overlapped with prior send's transit) ----
        float xn = 0.f, xd = 0.f;
        #pragma unroll
        for (int k = 0; k < CPL; k++) {
            float xv = sX[t][s * CPL + k];
            float tt = tanhf_a(fmaf(ssk[k], xv, sck[k]));
            float p  = fmaf(swe[k], tt, swe[k]);   // w_pos*erev*sigmoid
            xn += p; xd += fabsf(p);
        }

        #pragma unroll
        for (int u = 0; u < UNFOLDS; u++) {
            const int m  = u % 3;            // buffer holding v-set 6t+u
            const int mw = (u + 1) % 3;      // buffer receiving v-set 6t+u+1
            if (u != 0 || t != 0) {
                mbar_wait_(mbL[m], ph[m]); ph[m] ^= 1;
                if (tid == 0) mbar_expect_(mbL[m], TX_V);   // re-arm for next phase
            }
            // hoist the finalize operand LDS right after the wait
            float vv = sV[m][jg];
            // recurrent partial over my 8 pre-neurons (sensory folded in)
            float rn = xn, rd = xd;
            const float4* vb = (const float4*)&sV[m][s * IPL];
            float4 v0 = vb[0], v1 = vb[1];
            const float vi[IPL] = { v0.x, v0.y, v0.z, v0.w, v1.x, v1.y, v1.z, v1.w };
            #pragma unroll
            for (int k = 0; k < IPL; k++) {
                float tt = tanhf_a(fmaf(rs[k], vi[k], rc[k]));
                float p  = fmaf(rw[k], tt, rw[k]);
                rn += p; rd += fabsf(p);
            }
            // butterfly over the 16-lane group (all lanes end with full sums)
            #pragma unroll
            for (int d = 8; d >= 1; d >>= 1) {
                rn += __shfl_xor_sync(0xffffffffu, rn, d);
                rd += __shfl_xor_sync(0xffffffffu, rd, d);
            }
            // finalize v (every lane, redundantly)
            float num  = fmaf(pcm, vv, pcc) + rn;
            float den  = pa + rd + EPS_;
            float vnew = num * rcpf_(den);
            // broadcast: lanes 0..7 send this group's v to all 8 ranks (skip final set)
            if (sender && (t != T_ - 1 || u != UNFOLDS - 1))
                st_async_f32(addrV[mw], vnew, mbR[mw]);
            if (u == UNFOLDS - 1) {
                if (s == 0) out[((size_t)b * T_ + t) * U_ + jg] = fmaf(vnew, pow_, pob_);
                vlast = vnew;
            }
        }
    }
    if (s == 0) out[(size_t)B_ * T_ * U_ + b * U_ + jg] = vlast;   // h_final
    cluster_sync_();
}

// ---------------- launch ----------------
extern "C" void kernel_launch(void* const* d_in, const int* in_sizes, int n_in,
                              void* d_out, int out_size)
{
    const float* x     = (const float*)d_in[0];
    const float* h0    = (const float*)d_in[1];
    const float* gleak = (const float*)d_in[2];
    const float* vleak = (const float*)d_in[3];
    const float* cm    = (const float*)d_in[4];
    const float* sigma = (const float*)d_in[5];
    const float* mu    = (const float*)d_in[6];
    const float* w     = (const float*)d_in[7];
    const float* erev  = (const float*)d_in[8];
    const float* ssig  = (const float*)d_in[9];
    const float* smu   = (const float*)d_in[10];
    const float* sw    = (const float*)d_in[11];
    const float* serev = (const float*)d_in[12];
    const float* iw    = (const float*)d_in[13];
    const float* ib    = (const float*)d_in[14];
    const float* ow    = (const float*)d_in[15];
    const float* ob    = (const float*)d_in[16];

    ltc_prep<<<64, 256>>>(sigma, mu, w, erev, ssig, smu, sw, serev, iw, ib, gleak, vleak, cm);
    ltc_main<<<B_ * RANKS, NTH>>>(x, h0, ow, ob, (float*)d_out);
}